// round 8
// baseline (speedup 1.0000x reference)
#include <cuda_runtime.h>
#include <math.h>

#define DINLINE __device__ __forceinline__

// ---------------- scratch (device globals; no allocation allowed) ----------------
static __device__ float g_T[4 * 128 * 10 * 128];       // folded W_lin@W_skip, [l][u][v][w] (2.6 MB)
static __device__ float g_x[8000 * 128];               // node_feats @ W_up    (4.1 MB)
static __device__ float g_h3[128000 * 64];             // edge MLP hidden      (32.8 MB)
static __device__ float g_msg[8000 * 128 * 16];        // per-node messages    (65.5 MB)
static __device__ int   g_cnt[8192];                   // receiver histogram (zero-init; k_scan re-zeroes)
static __device__ int   g_off[8192];                   // exclusive offsets
static __device__ int   g_cur[8192];                   // scatter cursors
static __device__ int   g_perm[128000];                // edges sorted by receiver
static __device__ int   g_wq[4];                       // gather work queues (zero-init; k_scan re-zeroes)

// ---------------- helpers ----------------
typedef unsigned long long u64;
DINLINE u64 pk2(float x, float y) {
    u64 r;
    asm("mov.b64 %0, {%1,%2};" : "=l"(r) : "f"(x), "f"(y));
    return r;
}
DINLINE float2 upk2(u64 v) {
    float lo, hi;
    asm("mov.b64 {%0,%1}, %2;" : "=f"(lo), "=f"(hi) : "l"(v));
    return make_float2(lo, hi);
}
DINLINE void fma2(u64& d, u64 a, u64 b) {
    asm("fma.rn.f32x2 %0, %1, %2, %0;" : "+l"(d) : "l"(a), "l"(b));
}
DINLINE float silu(float x) { return x / (1.0f + __expf(-x)); }

// ================= K0: T[l][u][v][w] = sum_u2 W_lin[l][u,u2] * W_skip[l][u2,v,w] =================
__global__ __launch_bounds__(128) void k_T(const float* __restrict__ Wlin,
                                           const float* __restrict__ Wskip) {
    __shared__ float sw[128];
    int bx = blockIdx.x;               // l*1280 + u*10 + v
    int l = bx / 1280;
    int rem = bx % 1280;
    int u = rem / 10;
    int v = rem % 10;
    int w = threadIdx.x;
    sw[w] = Wlin[(l * 128 + u) * 128 + w];
    __syncthreads();
    const float* ws = Wskip + ((size_t)(l * 128) * 10 + v) * 128 + w;  // stride per u2 = 1280
    float a0 = 0.f, a1 = 0.f;
#pragma unroll 4
    for (int u2 = 0; u2 < 128; u2 += 2) {
        a0 += sw[u2] * ws[(size_t)u2 * 1280];
        a1 += sw[u2 + 1] * ws[(size_t)(u2 + 1) * 1280];
    }
    g_T[((size_t)(l * 128 + u) * 10 + v) * 128 + w] = a0 + a1;
}

// ================= K1+K2 merged: x-projection blocks then edge-MLP blocks =================
__global__ __launch_bounds__(128) void k_xmlp(const float* __restrict__ nf,
                                              const float* __restrict__ Wup,
                                              const float* __restrict__ ef,
                                              const float* __restrict__ W1,
                                              const float* __restrict__ W2,
                                              const float* __restrict__ W3,
                                              int N, int E, int xblocks) {
    extern __shared__ float sm1[];
    int t = threadIdx.x;
    if (blockIdx.x < xblocks) {
        // ---- x = node_feats @ W_up / sqrt(128) ----
        float* sW = sm1;             // 128*128
        float* srow = sm1 + 16384;   // 128
        const float sc = 0.08838834764831845f;  // 1/sqrt(128)
        for (int i = t; i < 16384; i += 128) sW[i] = Wup[i] * sc;
        __syncthreads();
        int n0 = blockIdx.x * 32;
        for (int r = 0; r < 32; r++) {
            int n = n0 + r;
            if (n >= N) break;
            __syncthreads();
            srow[t] = nf[(size_t)n * 128 + t];
            __syncthreads();
            float a0 = 0.f, a1 = 0.f, a2 = 0.f, a3 = 0.f;
#pragma unroll 8
            for (int k = 0; k < 128; k += 4) {
                a0 += srow[k] * sW[k * 128 + t];
                a1 += srow[k + 1] * sW[(k + 1) * 128 + t];
                a2 += srow[k + 2] * sW[(k + 2) * 128 + t];
                a3 += srow[k + 3] * sW[(k + 3) * 128 + t];
            }
            g_x[(size_t)n * 128 + t] = (a0 + a1) + (a2 + a3);
        }
        return;
    }
    // ---- edge MLP layers 1-3 ----
    float* s1 = sm1;          // 512
    float* s2 = sm1 + 512;    // 4096
    float* s3 = sm1 + 4608;   // 4096
    for (int i = t; i < 512; i += 128) s1[i] = W1[i] * 0.35355339059327373f;  // 1/sqrt(8)
    for (int i = t; i < 4096; i += 128) {
        s2[i] = W2[i] * 0.125f;
        s3[i] = W3[i] * 0.125f;
    }
    __syncthreads();
    int e = (blockIdx.x - xblocks) * 128 + t;
    if (e >= E) return;

    float4 i0 = *(const float4*)(ef + (size_t)e * 8);
    float4 i1 = *(const float4*)(ef + (size_t)e * 8 + 4);
    float in[8] = {i0.x, i0.y, i0.z, i0.w, i1.x, i1.y, i1.z, i1.w};

    u64 A[32], B[32];
#pragma unroll
    for (int j = 0; j < 32; j++) A[j] = 0ull;
#pragma unroll
    for (int k = 0; k < 8; k++) {
        u64 hh = pk2(in[k], in[k]);
        const ulonglong2* row = (const ulonglong2*)&s1[k * 64];
#pragma unroll
        for (int jj = 0; jj < 16; jj++) {
            ulonglong2 rv = row[jj];
            fma2(A[2 * jj], hh, rv.x);
            fma2(A[2 * jj + 1], hh, rv.y);
        }
    }
#pragma unroll
    for (int j = 0; j < 32; j++) {
        float2 q = upk2(A[j]);
        A[j] = pk2(silu(q.x), silu(q.y));
        B[j] = 0ull;
    }
#pragma unroll 4
    for (int kp = 0; kp < 32; kp++) {
        float2 hq = upk2(A[kp]);
        u64 h0 = pk2(hq.x, hq.x), h1 = pk2(hq.y, hq.y);
        const ulonglong2* r0 = (const ulonglong2*)&s2[(2 * kp) * 64];
        const ulonglong2* r1 = (const ulonglong2*)&s2[(2 * kp + 1) * 64];
#pragma unroll
        for (int jj = 0; jj < 16; jj++) {
            ulonglong2 a = r0[jj];
            ulonglong2 b = r1[jj];
            fma2(B[2 * jj], h0, a.x);
            fma2(B[2 * jj + 1], h0, a.y);
            fma2(B[2 * jj], h1, b.x);
            fma2(B[2 * jj + 1], h1, b.y);
        }
    }
#pragma unroll
    for (int j = 0; j < 32; j++) {
        float2 q = upk2(B[j]);
        B[j] = pk2(silu(q.x), silu(q.y));
        A[j] = 0ull;
    }
#pragma unroll 4
    for (int kp = 0; kp < 32; kp++) {
        float2 hq = upk2(B[kp]);
        u64 h0 = pk2(hq.x, hq.x), h1 = pk2(hq.y, hq.y);
        const ulonglong2* r0 = (const ulonglong2*)&s3[(2 * kp) * 64];
        const ulonglong2* r1 = (const ulonglong2*)&s3[(2 * kp + 1) * 64];
#pragma unroll
        for (int jj = 0; jj < 16; jj++) {
            ulonglong2 a = r0[jj];
            ulonglong2 b = r1[jj];
            fma2(A[2 * jj], h0, a.x);
            fma2(A[2 * jj + 1], h0, a.y);
            fma2(A[2 * jj], h1, b.x);
            fma2(A[2 * jj + 1], h1, b.y);
        }
    }
    float4* outp = (float4*)(g_h3 + (size_t)e * 64);
#pragma unroll
    for (int jj = 0; jj < 16; jj++) {
        float2 q0 = upk2(A[2 * jj]);
        float2 q1 = upk2(A[2 * jj + 1]);
        outp[jj] = make_float4(silu(q0.x), silu(q0.y), silu(q1.x), silu(q1.y));
    }
}

// ================= sort by receiver: hist -> scan -> perm =================
__global__ __launch_bounds__(256) void k_hist(const int* __restrict__ eidx, int E) {
    int e = blockIdx.x * 256 + threadIdx.x;
    if (e < E) atomicAdd(&g_cnt[eidx[E + e]], 1);
}

__global__ __launch_bounds__(1024) void k_scan() {
    __shared__ int wsum[32];
    int t = threadIdx.x, lane = t & 31, wid = t >> 5;
    int base = t * 8;
    int c[8], s = 0;
#pragma unroll
    for (int i = 0; i < 8; i++) { c[i] = s; s += g_cnt[base + i]; }
    int inc = s;
#pragma unroll
    for (int d = 1; d < 32; d <<= 1) {
        int o = __shfl_up_sync(0xffffffffu, inc, d);
        if (lane >= d) inc += o;
    }
    if (lane == 31) wsum[wid] = inc;
    __syncthreads();
    if (wid == 0) {
        int v = wsum[lane];
#pragma unroll
        for (int d = 1; d < 32; d <<= 1) {
            int o = __shfl_up_sync(0xffffffffu, v, d);
            if (lane >= d) v += o;
        }
        wsum[lane] = v;
    }
    __syncthreads();
    int excl = inc - s + (wid > 0 ? wsum[wid - 1] : 0);
#pragma unroll
    for (int i = 0; i < 8; i++) {
        int o = excl + c[i];
        g_off[base + i] = o;
        g_cur[base + i] = o;
        g_cnt[base + i] = 0;   // reset for next graph replay
    }
    if (t < 4) g_wq[t] = 0;    // reset gather work queues
}

__global__ __launch_bounds__(256) void k_perm(const int* __restrict__ eidx, int E) {
    int e = blockIdx.x * 256 + threadIdx.x;
    if (e < E) {
        int r = eidx[E + e];
        int p = atomicAdd(&g_cur[r], 1);
        g_perm[p] = e;
    }
}

// ================= K3: gather — per-node tp GEMM + register accumulation ==================
// blockIdx.y = cb (u-column block of 32). Warps pop node-batches of 2 from g_wq[cb].
__global__ __launch_bounds__(128, 4) void k_gather(const float* __restrict__ ea,
                                                   const float* __restrict__ cutoff,
                                                   const int* __restrict__ eidx,
                                                   const float* __restrict__ W4,
                                                   int N, int E) {
    extern __shared__ float smg[];
    float* sW4 = smg;                     // 8192 floats (32KB)
    float* sh3 = smg + 8192;              // 4 warps * 8 edges * 64 = 2048 floats
    int* sperm = (int*)(smg + 8192 + 2048);  // 4 warps * 8
    int t = threadIdx.x, wrp = t >> 5, lane = t & 31;
    int cb = blockIdx.y;

    for (int i = t; i < 8192; i += 128)
        sW4[i] = W4[(i >> 7) * 512 + (cb << 7) + (i & 127)] * 0.125f;
    __syncthreads();

    const int* snd = eidx;
    int u_lane = (cb << 5) + lane;
    float* mh3 = sh3 + wrp * 512;
    int* mperm = sperm + wrp * 8;

    for (;;) {
        int nb;
        if (lane == 0) nb = atomicAdd(&g_wq[cb], 2);
        nb = __shfl_sync(0xffffffffu, nb, 0);
        if (nb >= N) break;
        int nend = min(nb + 2, N);

        for (int n = nb; n < nend; n++) {
            int o0 = g_off[n], o1 = g_off[n + 1];
            u64 nacc[8];
#pragma unroll
            for (int j = 0; j < 8; j++) nacc[j] = 0ull;

            for (int ob = o0; ob < o1; ob += 8) {
                int ne = min(8, o1 - ob);
                if (lane < ne) mperm[lane] = g_perm[ob + lane];
                __syncwarp();
                for (int i = lane; i < ne * 16; i += 32) {
                    int el = i >> 4, q = i & 15;
                    ((float4*)mh3)[i] = *(const float4*)(g_h3 + (size_t)mperm[el] * 64 + q * 4);
                }
                __syncwarp();

                u64 acc[8][2];
#pragma unroll
                for (int e = 0; e < 8; e++) { acc[e][0] = 0ull; acc[e][1] = 0ull; }

#pragma unroll 1
                for (int k = 0; k < 64; k += 4) {
                    float4 h4[8];
#pragma unroll
                    for (int e = 0; e < 8; e++) h4[e] = *(const float4*)&mh3[e * 64 + k];
#pragma unroll
                    for (int kk = 0; kk < 4; kk++) {
                        float4 wv = *(const float4*)&sW4[(k + kk) * 128 + lane * 4];
                        u64 w01 = pk2(wv.x, wv.y);
                        u64 w23 = pk2(wv.z, wv.w);
#pragma unroll
                        for (int e = 0; e < 8; e++) {
                            float hv = (kk == 0) ? h4[e].x : (kk == 1) ? h4[e].y
                                     : (kk == 2) ? h4[e].z : h4[e].w;
                            u64 hh = pk2(hv, hv);
                            fma2(acc[e][0], hh, w01);
                            fma2(acc[e][1], hh, w23);
                        }
                    }
                }

                for (int e = 0; e < ne; e++) {
                    int ei = mperm[e];
                    int s = snd[ei];
                    float cf = cutoff[ei];
                    const float4* eap = (const float4*)(ea + (size_t)ei * 16);
                    float4 ea0 = __ldg(eap + 0);
                    float4 ea1 = __ldg(eap + 1);
                    float4 ea2 = __ldg(eap + 2);
                    float4 ea3 = __ldg(eap + 3);
                    float xs = g_x[(size_t)s * 128 + u_lane] * cf;
                    float2 p01 = upk2(acc[e][0]);
                    float2 p23 = upk2(acc[e][1]);
                    float v0 = p01.x * xs, v1 = p01.y * xs, v2 = p23.x * xs, v3 = p23.y * xs;
                    // LM_L = [0, 1,1,1, 2,2,2,2,2, 3,3,3,3,3,3,3]
                    fma2(nacc[0], pk2(v0, v1), pk2(ea0.x, ea0.y));
                    fma2(nacc[1], pk2(v1, v1), pk2(ea0.z, ea0.w));
                    fma2(nacc[2], pk2(v2, v2), pk2(ea1.x, ea1.y));
                    fma2(nacc[3], pk2(v2, v2), pk2(ea1.z, ea1.w));
                    fma2(nacc[4], pk2(v2, v3), pk2(ea2.x, ea2.y));
                    fma2(nacc[5], pk2(v3, v3), pk2(ea2.z, ea2.w));
                    fma2(nacc[6], pk2(v3, v3), pk2(ea3.x, ea3.y));
                    fma2(nacc[7], pk2(v3, v3), pk2(ea3.z, ea3.w));
                }
                __syncwarp();
            }

            float4* dst = (float4*)(g_msg + (size_t)n * 2048 + u_lane * 16);
#pragma unroll
            for (int j = 0; j < 4; j++) {
                float2 a = upk2(nacc[2 * j]);
                float2 b = upk2(nacc[2 * j + 1]);
                dst[j] = make_float4(a.x, a.y, b.x, b.y);
            }
        }
    }
}

// ================= K4: out[n,w,m] = c * sum_u msg[n,u,m] * (sum_v attrs[n,v]*T[l(m)][u,v,w]) ====
// 256 threads: 2 pair-groups of 128 w-threads; each group owns 4 node-pairs over ALL u.
// 16 nodes/CTA halves T L2-traffic; both groups stream identical T addresses (L1 dedup),
// kept in lockstep with a sync every 32 u.
__global__ __launch_bounds__(256) void k_out(const float* __restrict__ attrs,
                                             float* __restrict__ out, float c, int N) {
    extern __shared__ float sm4[];
    float2* smsg = (float2*)sm4;          // 8 pairs * 2048 float2 = 128KB
    int t = threadIdx.x, grp = t >> 7, w = t & 127;
    int n0 = blockIdx.x * 16;
    if (n0 >= N) return;

    // stage 16 nodes as 8 interleaved pairs (256 threads)
#pragma unroll
    for (int p = 0; p < 8; p++) {
        const float4* rA = (const float4*)(g_msg + (size_t)(n0 + 2 * p) * 2048);
        const float4* rB = rA + 512;
        float2* dst = smsg + p * 2048;
        for (int i = t; i < 512; i += 256) {
            float4 a = rA[i];
            float4 b = rB[i];
            dst[4 * i + 0] = make_float2(a.x, b.x);
            dst[4 * i + 1] = make_float2(a.y, b.y);
            dst[4 * i + 2] = make_float2(a.z, b.z);
            dst[4 * i + 3] = make_float2(a.w, b.w);
        }
    }
    __syncthreads();

    int p0 = grp * 4;  // this group's 4 pairs
    u64 at2[4][10];
#pragma unroll
    for (int p = 0; p < 4; p++)
#pragma unroll
        for (int v = 0; v < 10; v++)
            at2[p][v] = pk2(attrs[(size_t)(n0 + 2 * (p0 + p)) * 10 + v],
                            attrs[(size_t)(n0 + 2 * (p0 + p) + 1) * 10 + v]);

#pragma unroll
    for (int l = 0; l < 4; l++) {
        const int Ld = (l == 0) ? 1 : (l == 1) ? 3 : (l == 2) ? 5 : 7;
        const int m0 = (l == 0) ? 0 : (l == 1) ? 1 : (l == 2) ? 4 : 9;
        u64 acc[4][7];
#pragma unroll
        for (int p = 0; p < 4; p++)
#pragma unroll
            for (int mm = 0; mm < 7; mm++) acc[p][mm] = 0ull;

        const float* Tl = g_T + (size_t)l * 163840 + w;
#pragma unroll 1
        for (int u = 0; u < 128; u++) {
            const float* tp = Tl + (size_t)u * 1280;
            u64 tvv[10];
#pragma unroll
            for (int v = 0; v < 10; v++) {
                float tv = tp[v * 128];
                tvv[v] = pk2(tv, tv);
            }
#pragma unroll
            for (int p = 0; p < 4; p++) {
                u64 S = 0ull;
#pragma unroll
                for (int v = 0; v < 10; v++) fma2(S, at2[p][v], tvv[v]);
                const float2* mrow = smsg + (p0 + p) * 2048 + u * 16 + m0;
#pragma unroll
                for (int mm = 0; mm < Ld; mm++) {
                    float2 q = mrow[mm];
                    fma2(acc[p][mm], pk2(q.x, q.y), S);
                }
            }
            if ((u & 31) == 31) __syncthreads();  // keep the two groups T-lockstep for L1 reuse
        }
        // store this l-block (groups write disjoint nodes)
#pragma unroll
        for (int p = 0; p < 4; p++) {
            int nA = n0 + 2 * (p0 + p);
            float* oA = out + (size_t)nA * 2048 + w * 16 + m0;
            float* oB = oA + 2048;
#pragma unroll
            for (int mm = 0; mm < 7; mm++) {
                if (mm < Ld) {
                    float2 q = upk2(acc[p][mm]);
                    oA[mm] = q.x * c;
                    oB[mm] = q.y * c;
                }
            }
        }
    }
}

// ================= host =================
extern "C" void kernel_launch(void* const* d_in, const int* in_sizes, int n_in,
                              void* d_out, int out_size) {
    const float* node_attrs = (const float*)d_in[0];
    const float* node_feats = (const float*)d_in[1];
    const float* edge_attrs = (const float*)d_in[2];
    const float* edge_feats = (const float*)d_in[3];
    const int* edge_index = (const int*)d_in[4];
    const float* cutoff = (const float*)d_in[5];
    const float* W_up = (const float*)d_in[6];
    const float* W1 = (const float*)d_in[7];
    const float* W2 = (const float*)d_in[8];
    const float* W3 = (const float*)d_in[9];
    const float* W4 = (const float*)d_in[10];
    const float* W_lin = (const float*)d_in[11];
    const float* W_skip = (const float*)d_in[12];
    float* out = (float*)d_out;

    int N = in_sizes[1] / 128;
    int E = in_sizes[5];
    int xblocks = (N + 31) / 32;

    cudaFuncSetAttribute(k_xmlp, cudaFuncAttributeMaxDynamicSharedMemorySize, 66048);
    cudaFuncSetAttribute(k_gather, cudaFuncAttributeMaxDynamicSharedMemorySize, 41088);
    cudaFuncSetAttribute(k_out, cudaFuncAttributeMaxDynamicSharedMemorySize, 131072);

    // launch order puts k_gather 5th (ncu capture slot)
    k_hist<<<(E + 255) / 256, 256>>>(edge_index, E);
    k_scan<<<1, 1024>>>();
    k_perm<<<(E + 255) / 256, 256>>>(edge_index, E);
    k_xmlp<<<xblocks + (E + 127) / 128, 128, 66048>>>(node_feats, W_up, edge_feats,
                                                      W1, W2, W3, N, E, xblocks);
    dim3 gg(148, 4);
    k_gather<<<gg, 128, 41088>>>(edge_attrs, cutoff, edge_index, W4, N, E);

    k_T<<<5120, 128>>>(W_lin, W_skip);

    float cfin = (float)(1.0 / (16.0 * sqrt(128.0 * 1280.0)));
    k_out<<<(N + 15) / 16, 256, 131072>>>(node_attrs, out, cfin, N);
}

// round 9
// speedup vs baseline: 1.5086x; 1.5086x over previous
#include <cuda_runtime.h>
#include <math.h>

#define DINLINE __device__ __forceinline__

// ---------------- scratch (device globals; no allocation allowed) ----------------
static __device__ float g_T[4 * 128 * 10 * 128];       // folded W_lin@W_skip, [l][u][v][w] (2.6 MB)
static __device__ float g_x[8000 * 128];               // node_feats @ W_up    (4.1 MB)
static __device__ float g_h3[128000 * 64];             // edge MLP hidden      (32.8 MB)
static __device__ float g_msg[8000 * 128 * 16];        // per-node messages    (65.5 MB)
static __device__ int   g_cnt[8192];                   // receiver histogram (zero-init; k_scan re-zeroes)
static __device__ int   g_off[8192];                   // exclusive offsets
static __device__ int   g_cur[8192];                   // scatter cursors
static __device__ int   g_perm[128000];                // edges sorted by receiver
static __device__ int   g_wq[4];                       // gather work queues (zero-init; k_scan re-zeroes)

// ---------------- helpers ----------------
typedef unsigned long long u64;
DINLINE u64 pk2(float x, float y) {
    u64 r;
    asm("mov.b64 %0, {%1,%2};" : "=l"(r) : "f"(x), "f"(y));
    return r;
}
DINLINE float2 upk2(u64 v) {
    float lo, hi;
    asm("mov.b64 {%0,%1}, %2;" : "=f"(lo), "=f"(hi) : "l"(v));
    return make_float2(lo, hi);
}
DINLINE void fma2(u64& d, u64 a, u64 b) {
    asm("fma.rn.f32x2 %0, %1, %2, %0;" : "+l"(d) : "l"(a), "l"(b));
}
DINLINE float silu(float x) { return x / (1.0f + __expf(-x)); }

// ================= K0: T[l][u][v][w] = sum_u2 W_lin[l][u,u2] * W_skip[l][u2,v,w] =================
__global__ __launch_bounds__(128) void k_T(const float* __restrict__ Wlin,
                                           const float* __restrict__ Wskip) {
    __shared__ float sw[128];
    int bx = blockIdx.x;               // l*1280 + u*10 + v
    int l = bx / 1280;
    int rem = bx % 1280;
    int u = rem / 10;
    int v = rem % 10;
    int w = threadIdx.x;
    sw[w] = Wlin[(l * 128 + u) * 128 + w];
    __syncthreads();
    const float* ws = Wskip + ((size_t)(l * 128) * 10 + v) * 128 + w;  // stride per u2 = 1280
    float a0 = 0.f, a1 = 0.f;
#pragma unroll 4
    for (int u2 = 0; u2 < 128; u2 += 2) {
        a0 += sw[u2] * ws[(size_t)u2 * 1280];
        a1 += sw[u2 + 1] * ws[(size_t)(u2 + 1) * 1280];
    }
    g_T[((size_t)(l * 128 + u) * 10 + v) * 128 + w] = a0 + a1;
}

// ================= K1: x = node_feats @ W_up / sqrt(128) =================
__global__ __launch_bounds__(128) void k_x(const float* __restrict__ nf,
                                           const float* __restrict__ Wup, int N) {
    extern __shared__ float sm1[];
    float* sW = sm1;             // 128*128
    float* srow = sm1 + 16384;   // 128
    int t = threadIdx.x;
    const float sc = 0.08838834764831845f;  // 1/sqrt(128)
    for (int i = t; i < 16384; i += 128) sW[i] = Wup[i] * sc;
    __syncthreads();
    int n0 = blockIdx.x * 32;
    for (int r = 0; r < 32; r++) {
        int n = n0 + r;
        if (n >= N) break;
        __syncthreads();
        srow[t] = nf[(size_t)n * 128 + t];
        __syncthreads();
        float a0 = 0.f, a1 = 0.f, a2 = 0.f, a3 = 0.f;
#pragma unroll 8
        for (int k = 0; k < 128; k += 4) {
            a0 += srow[k] * sW[k * 128 + t];
            a1 += srow[k + 1] * sW[(k + 1) * 128 + t];
            a2 += srow[k + 2] * sW[(k + 2) * 128 + t];
            a3 += srow[k + 3] * sW[(k + 3) * 128 + t];
        }
        g_x[(size_t)n * 128 + t] = (a0 + a1) + (a2 + a3);
    }
}

// ================= K2: edge MLP layers 1-3, packed f32x2 (thread per edge) =================
__global__ __launch_bounds__(128) void k_mlp(const float* __restrict__ ef,
                                             const float* __restrict__ W1,
                                             const float* __restrict__ W2,
                                             const float* __restrict__ W3, int E) {
    __shared__ __align__(16) float s1[512];
    __shared__ __align__(16) float s2[4096];
    __shared__ __align__(16) float s3[4096];
    int t = threadIdx.x;
    for (int i = t; i < 512; i += 128) s1[i] = W1[i] * 0.35355339059327373f;  // 1/sqrt(8)
    for (int i = t; i < 4096; i += 128) {
        s2[i] = W2[i] * 0.125f;
        s3[i] = W3[i] * 0.125f;
    }
    __syncthreads();
    int e = blockIdx.x * 128 + t;
    if (e >= E) return;

    float4 i0 = *(const float4*)(ef + (size_t)e * 8);
    float4 i1 = *(const float4*)(ef + (size_t)e * 8 + 4);
    float in[8] = {i0.x, i0.y, i0.z, i0.w, i1.x, i1.y, i1.z, i1.w};

    u64 A[32], B[32];
#pragma unroll
    for (int j = 0; j < 32; j++) A[j] = 0ull;
#pragma unroll
    for (int k = 0; k < 8; k++) {
        u64 hh = pk2(in[k], in[k]);
        const ulonglong2* row = (const ulonglong2*)&s1[k * 64];
#pragma unroll
        for (int jj = 0; jj < 16; jj++) {
            ulonglong2 rv = row[jj];
            fma2(A[2 * jj], hh, rv.x);
            fma2(A[2 * jj + 1], hh, rv.y);
        }
    }
#pragma unroll
    for (int j = 0; j < 32; j++) {
        float2 q = upk2(A[j]);
        A[j] = pk2(silu(q.x), silu(q.y));
        B[j] = 0ull;
    }
#pragma unroll 4
    for (int kp = 0; kp < 32; kp++) {
        float2 hq = upk2(A[kp]);
        u64 h0 = pk2(hq.x, hq.x), h1 = pk2(hq.y, hq.y);
        const ulonglong2* r0 = (const ulonglong2*)&s2[(2 * kp) * 64];
        const ulonglong2* r1 = (const ulonglong2*)&s2[(2 * kp + 1) * 64];
#pragma unroll
        for (int jj = 0; jj < 16; jj++) {
            ulonglong2 a = r0[jj];
            ulonglong2 b = r1[jj];
            fma2(B[2 * jj], h0, a.x);
            fma2(B[2 * jj + 1], h0, a.y);
            fma2(B[2 * jj], h1, b.x);
            fma2(B[2 * jj + 1], h1, b.y);
        }
    }
#pragma unroll
    for (int j = 0; j < 32; j++) {
        float2 q = upk2(B[j]);
        B[j] = pk2(silu(q.x), silu(q.y));
        A[j] = 0ull;
    }
#pragma unroll 4
    for (int kp = 0; kp < 32; kp++) {
        float2 hq = upk2(B[kp]);
        u64 h0 = pk2(hq.x, hq.x), h1 = pk2(hq.y, hq.y);
        const ulonglong2* r0 = (const ulonglong2*)&s3[(2 * kp) * 64];
        const ulonglong2* r1 = (const ulonglong2*)&s3[(2 * kp + 1) * 64];
#pragma unroll
        for (int jj = 0; jj < 16; jj++) {
            ulonglong2 a = r0[jj];
            ulonglong2 b = r1[jj];
            fma2(A[2 * jj], h0, a.x);
            fma2(A[2 * jj + 1], h0, a.y);
            fma2(A[2 * jj], h1, b.x);
            fma2(A[2 * jj + 1], h1, b.y);
        }
    }
    float4* outp = (float4*)(g_h3 + (size_t)e * 64);
#pragma unroll
    for (int jj = 0; jj < 16; jj++) {
        float2 q0 = upk2(A[2 * jj]);
        float2 q1 = upk2(A[2 * jj + 1]);
        outp[jj] = make_float4(silu(q0.x), silu(q0.y), silu(q1.x), silu(q1.y));
    }
}

// ================= sort by receiver: hist -> scan -> perm =================
__global__ __launch_bounds__(256) void k_hist(const int* __restrict__ eidx, int E) {
    int e = blockIdx.x * 256 + threadIdx.x;
    if (e < E) atomicAdd(&g_cnt[eidx[E + e]], 1);
}

__global__ __launch_bounds__(1024) void k_scan() {
    __shared__ int wsum[32];
    int t = threadIdx.x, lane = t & 31, wid = t >> 5;
    int base = t * 8;
    int c[8], s = 0;
#pragma unroll
    for (int i = 0; i < 8; i++) { c[i] = s; s += g_cnt[base + i]; }
    int inc = s;
#pragma unroll
    for (int d = 1; d < 32; d <<= 1) {
        int o = __shfl_up_sync(0xffffffffu, inc, d);
        if (lane >= d) inc += o;
    }
    if (lane == 31) wsum[wid] = inc;
    __syncthreads();
    if (wid == 0) {
        int v = wsum[lane];
#pragma unroll
        for (int d = 1; d < 32; d <<= 1) {
            int o = __shfl_up_sync(0xffffffffu, v, d);
            if (lane >= d) v += o;
        }
        wsum[lane] = v;
    }
    __syncthreads();
    int excl = inc - s + (wid > 0 ? wsum[wid - 1] : 0);
#pragma unroll
    for (int i = 0; i < 8; i++) {
        int o = excl + c[i];
        g_off[base + i] = o;
        g_cur[base + i] = o;
        g_cnt[base + i] = 0;   // reset for next graph replay
    }
    if (t < 4) g_wq[t] = 0;    // reset gather work queues
}

__global__ __launch_bounds__(256) void k_perm(const int* __restrict__ eidx, int E) {
    int e = blockIdx.x * 256 + threadIdx.x;
    if (e < E) {
        int r = eidx[E + e];
        int p = atomicAdd(&g_cur[r], 1);
        g_perm[p] = e;
    }
}

// ================= K3: gather — per-node tp GEMM + register accumulation ==================
// blockIdx.y = cb (u-column block of 32). Warps pop node-batches of 2 from g_wq[cb].
__global__ __launch_bounds__(128, 4) void k_gather(const float* __restrict__ ea,
                                                   const float* __restrict__ cutoff,
                                                   const int* __restrict__ eidx,
                                                   const float* __restrict__ W4,
                                                   int N, int E) {
    extern __shared__ float smg[];
    float* sW4 = smg;                     // 8192 floats (32KB)
    float* sh3 = smg + 8192;              // 4 warps * 8 edges * 64 = 2048 floats
    int* sperm = (int*)(smg + 8192 + 2048);  // 4 warps * 8
    int t = threadIdx.x, wrp = t >> 5, lane = t & 31;
    int cb = blockIdx.y;

    for (int i = t; i < 8192; i += 128)
        sW4[i] = W4[(i >> 7) * 512 + (cb << 7) + (i & 127)] * 0.125f;
    __syncthreads();

    const int* snd = eidx;
    int u_lane = (cb << 5) + lane;
    float* mh3 = sh3 + wrp * 512;
    int* mperm = sperm + wrp * 8;

    for (;;) {
        int nb;
        if (lane == 0) nb = atomicAdd(&g_wq[cb], 2);
        nb = __shfl_sync(0xffffffffu, nb, 0);
        if (nb >= N) break;
        int nend = min(nb + 2, N);

        for (int n = nb; n < nend; n++) {
            int o0 = g_off[n], o1 = g_off[n + 1];
            u64 nacc[8];
#pragma unroll
            for (int j = 0; j < 8; j++) nacc[j] = 0ull;

            for (int ob = o0; ob < o1; ob += 8) {
                int ne = min(8, o1 - ob);
                if (lane < ne) mperm[lane] = g_perm[ob + lane];
                __syncwarp();
                for (int i = lane; i < ne * 16; i += 32) {
                    int el = i >> 4, q = i & 15;
                    ((float4*)mh3)[i] = *(const float4*)(g_h3 + (size_t)mperm[el] * 64 + q * 4);
                }
                __syncwarp();

                u64 acc[8][2];
#pragma unroll
                for (int e = 0; e < 8; e++) { acc[e][0] = 0ull; acc[e][1] = 0ull; }

#pragma unroll 1
                for (int k = 0; k < 64; k += 4) {
                    float4 h4[8];
#pragma unroll
                    for (int e = 0; e < 8; e++) h4[e] = *(const float4*)&mh3[e * 64 + k];
#pragma unroll
                    for (int kk = 0; kk < 4; kk++) {
                        float4 wv = *(const float4*)&sW4[(k + kk) * 128 + lane * 4];
                        u64 w01 = pk2(wv.x, wv.y);
                        u64 w23 = pk2(wv.z, wv.w);
#pragma unroll
                        for (int e = 0; e < 8; e++) {
                            float hv = (kk == 0) ? h4[e].x : (kk == 1) ? h4[e].y
                                     : (kk == 2) ? h4[e].z : h4[e].w;
                            u64 hh = pk2(hv, hv);
                            fma2(acc[e][0], hh, w01);
                            fma2(acc[e][1], hh, w23);
                        }
                    }
                }

                for (int e = 0; e < ne; e++) {
                    int ei = mperm[e];
                    int s = snd[ei];
                    float cf = cutoff[ei];
                    const float4* eap = (const float4*)(ea + (size_t)ei * 16);
                    float4 ea0 = __ldg(eap + 0);
                    float4 ea1 = __ldg(eap + 1);
                    float4 ea2 = __ldg(eap + 2);
                    float4 ea3 = __ldg(eap + 3);
                    float xs = g_x[(size_t)s * 128 + u_lane] * cf;
                    float2 p01 = upk2(acc[e][0]);
                    float2 p23 = upk2(acc[e][1]);
                    float v0 = p01.x * xs, v1 = p01.y * xs, v2 = p23.x * xs, v3 = p23.y * xs;
                    // LM_L = [0, 1,1,1, 2,2,2,2,2, 3,3,3,3,3,3,3]
                    fma2(nacc[0], pk2(v0, v1), pk2(ea0.x, ea0.y));
                    fma2(nacc[1], pk2(v1, v1), pk2(ea0.z, ea0.w));
                    fma2(nacc[2], pk2(v2, v2), pk2(ea1.x, ea1.y));
                    fma2(nacc[3], pk2(v2, v2), pk2(ea1.z, ea1.w));
                    fma2(nacc[4], pk2(v2, v3), pk2(ea2.x, ea2.y));
                    fma2(nacc[5], pk2(v3, v3), pk2(ea2.z, ea2.w));
                    fma2(nacc[6], pk2(v3, v3), pk2(ea3.x, ea3.y));
                    fma2(nacc[7], pk2(v3, v3), pk2(ea3.z, ea3.w));
                }
                __syncwarp();
            }

            float4* dst = (float4*)(g_msg + (size_t)n * 2048 + u_lane * 16);
#pragma unroll
            for (int j = 0; j < 4; j++) {
                float2 a = upk2(nacc[2 * j]);
                float2 b = upk2(nacc[2 * j + 1]);
                dst[j] = make_float4(a.x, a.y, b.x, b.y);
            }
        }
    }
}

// ================= K4: out[n,w,m] = c * sum_u msg[n,u,m] * (sum_v attrs[n,v]*T[l(m)][u,v,w]) ====
// 256 threads: 2 u-groups of 128 w-threads. 8 nodes = 4 packed pairs. Cross-group smem reduce.
// T layout [l][u][v][w]: w = thread index -> fully coalesced LDG.32 (1 wavefront per v).
__global__ __launch_bounds__(256) void k_out(const float* __restrict__ attrs,
                                             float* __restrict__ out, float c, int N) {
    extern __shared__ float sm4[];
    float2* smsg = (float2*)sm4;          // 4 pairs * 2048 float2 = 64KB
    u64* sred = (u64*)(sm4 + 16384);      // 4p*7m*128w u64 = 28KB
    int t = threadIdx.x, grp = t >> 7, w = t & 127;
    int n0 = blockIdx.x * 8;
    if (n0 >= N) return;

    // stage msg: pair-interleave rows of g_msg (256 threads)
#pragma unroll
    for (int p = 0; p < 4; p++) {
        const float4* rA = (const float4*)(g_msg + (size_t)(n0 + 2 * p) * 2048);
        const float4* rB = rA + 512;
        float2* dst = smsg + p * 2048;
        for (int i = t; i < 512; i += 256) {
            float4 a = rA[i];
            float4 b = rB[i];
            dst[4 * i + 0] = make_float2(a.x, b.x);
            dst[4 * i + 1] = make_float2(a.y, b.y);
            dst[4 * i + 2] = make_float2(a.z, b.z);
            dst[4 * i + 3] = make_float2(a.w, b.w);
        }
    }
    __syncthreads();

    u64 at2[4][10];
#pragma unroll
    for (int p = 0; p < 4; p++)
#pragma unroll
        for (int v = 0; v < 10; v++)
            at2[p][v] = pk2(attrs[(size_t)(n0 + 2 * p) * 10 + v],
                            attrs[(size_t)(n0 + 2 * p + 1) * 10 + v]);

    int u0 = grp << 6;  // group 0: u 0..63, group 1: u 64..127
#pragma unroll
    for (int l = 0; l < 4; l++) {
        const int Ld = (l == 0) ? 1 : (l == 1) ? 3 : (l == 2) ? 5 : 7;
        const int m0 = (l == 0) ? 0 : (l == 1) ? 1 : (l == 2) ? 4 : 9;
        u64 acc[4][7];
#pragma unroll
        for (int p = 0; p < 4; p++)
#pragma unroll
            for (int mm = 0; mm < 7; mm++) acc[p][mm] = 0ull;

        const float* Tl = g_T + (size_t)l * 163840 + (size_t)u0 * 1280 + w;
#pragma unroll 2
        for (int du = 0; du < 64; du++) {
            const float* tp = Tl + (size_t)du * 1280;
            u64 tvv[10];
#pragma unroll
            for (int v = 0; v < 10; v++) {
                float tv = tp[v * 128];     // coalesced: consecutive w threads -> consecutive addrs
                tvv[v] = pk2(tv, tv);
            }
            int u = u0 + du;
#pragma unroll
            for (int p = 0; p < 4; p++) {
                u64 S = 0ull;
#pragma unroll
                for (int v = 0; v < 10; v++) fma2(S, at2[p][v], tvv[v]);
                const float2* mrow = smsg + p * 2048 + u * 16 + m0;
#pragma unroll
                for (int mm = 0; mm < Ld; mm++) {
                    float2 q = mrow[mm];
                    fma2(acc[p][mm], pk2(q.x, q.y), S);
                }
            }
        }
        // cross-group reduction: group 1 publishes, group 0 adds + stores
        if (grp == 1) {
#pragma unroll
            for (int p = 0; p < 4; p++)
#pragma unroll
                for (int mm = 0; mm < 7; mm++)
                    if (mm < Ld) sred[(p * 7 + mm) * 128 + w] = acc[p][mm];
        }
        __syncthreads();
        if (grp == 0) {
#pragma unroll
            for (int p = 0; p < 4; p++) {
                int nA = n0 + 2 * p;
                float* oA = out + (size_t)nA * 2048 + w * 16 + m0;
                float* oB = oA + 2048;
#pragma unroll
                for (int mm = 0; mm < 7; mm++) {
                    if (mm < Ld) {
                        float2 q = upk2(acc[p][mm]);
                        float2 r = upk2(sred[(p * 7 + mm) * 128 + w]);
                        oA[mm] = (q.x + r.x) * c;
                        oB[mm] = (q.y + r.y) * c;
                    }
                }
            }
        }
        __syncthreads();  // sred safe to reuse for next l
    }
}

// ================= host =================
extern "C" void kernel_launch(void* const* d_in, const int* in_sizes, int n_in,
                              void* d_out, int out_size) {
    const float* node_attrs = (const float*)d_in[0];
    const float* node_feats = (const float*)d_in[1];
    const float* edge_attrs = (const float*)d_in[2];
    const float* edge_feats = (const float*)d_in[3];
    const int* edge_index = (const int*)d_in[4];
    const float* cutoff = (const float*)d_in[5];
    const float* W_up = (const float*)d_in[6];
    const float* W1 = (const float*)d_in[7];
    const float* W2 = (const float*)d_in[8];
    const float* W3 = (const float*)d_in[9];
    const float* W4 = (const float*)d_in[10];
    const float* W_lin = (const float*)d_in[11];
    const float* W_skip = (const float*)d_in[12];
    float* out = (float*)d_out;

    int N = in_sizes[1] / 128;
    int E = in_sizes[5];

    cudaFuncSetAttribute(k_x, cudaFuncAttributeMaxDynamicSharedMemorySize, 66048);
    cudaFuncSetAttribute(k_gather, cudaFuncAttributeMaxDynamicSharedMemorySize, 41088);
    cudaFuncSetAttribute(k_out, cudaFuncAttributeMaxDynamicSharedMemorySize, 94208);

    // slot 4 = k_mlp (ncu capture)
    k_hist<<<(E + 255) / 256, 256>>>(edge_index, E);
    k_scan<<<1, 1024>>>();
    k_perm<<<(E + 255) / 256, 256>>>(edge_index, E);
    k_mlp<<<(E + 127) / 128, 128>>>(edge_feats, W1, W2, W3, E);
    k_x<<<(N + 31) / 32, 128, 66048>>>(node_feats, W_up, N);

    dim3 gg(148, 4);
    k_gather<<<gg, 128, 41088>>>(edge_attrs, cutoff, edge_index, W4, N, E);

    k_T<<<5120, 128>>>(W_lin, W_skip);

    float cfin = (float)(1.0 / (16.0 * sqrt(128.0 * 1280.0)));
    k_out<<<(N + 7) / 8, 256, 94208>>>(node_attrs, out, cfin, N);
}